// round 5
// baseline (speedup 1.0000x reference)
#include <cuda_runtime.h>
#include <math.h>
#include <stdint.h>

#define NB   4
#define NC   512
#define HWs  4096
#define NA   36864
#define NSORT 65536
#define NIN  6000
#define NWRD 94
#define NPAD 6016
#define NOUTP 300
#define KTOT 4608

#define OFF_LOCS 294912
#define OFF_ROIS 884736
#define OFF_INDS 889536
#define OFF_ANCH 890736

typedef unsigned long long u64;

// ---------------- scratch ----------------
__device__ float g_h[(size_t)NB * NC * HWs];   // [b][oc][sp] (channel-major, as R1)
__device__ float2 g_w2[(size_t)NC * KTOT];     // duplicated weights {w,w}
__device__ float g_rois[(size_t)NB * NA * 4];
__device__ unsigned char g_valid[NB * NA];
__device__ u64 g_keys[NB * NSORT];
__device__ float g_rois_s[NB * NPAD * 4];
__device__ unsigned char g_valid_s[NB * NPAD];
__device__ u64 g_mask[(size_t)NB * NIN * NWRD];
__device__ unsigned char g_keep[NB * NIN];

__device__ __forceinline__ u64 fma2(u64 a, u64 b, u64 c) {
    u64 d;
    asm("fma.rn.f32x2 %0, %1, %2, %3;" : "=l"(d) : "l"(a), "l"(b), "l"(c));
    return d;
}

// ---------------- weight duplication ----------------
__global__ void prep_w2_kernel(const float* __restrict__ w) {
    int gid = blockIdx.x * blockDim.x + threadIdx.x;
    if (gid >= NC * KTOT) return;
    float v = w[gid];
    g_w2[gid] = make_float2(v, v);
}

// ---------------- f32x2 conv 3x3 + bias + relu ----------------
// grid (16 tiles, 16 oc-groups of 32, 4 batch), 256 threads.
// thread: oc-lane o = tid&7 (q<4 -> oc = o+8q), sp-lane s = tid>>3:
//   px = s&7 (x-pair 2px,2px+1), py0 = s>>3, rows py0+4p (p<4).
#define SMEM_IN_FLOATS (16 * 324)
#define SMEM_W2_OFF    (SMEM_IN_FLOATS * 4)              // 20736 bytes
#define SMEM_CONV_TOTAL (SMEM_W2_OFF + 32 * 144 * 8)     // + 36864 = 57600

__global__ void __launch_bounds__(256) conv_f32x2_kernel(const float* __restrict__ x,
                                                         const float* __restrict__ bias) {
    extern __shared__ char smem_raw[];
    float*  s_in = (float*)smem_raw;
    float2* s_w2 = (float2*)(smem_raw + SMEM_W2_OFF);

    int tid = threadIdx.x;
    int b = blockIdx.z, ocg = blockIdx.y;
    int ty0 = (blockIdx.x >> 2) << 4;
    int tx0 = (blockIdx.x & 3) << 4;
    int o = tid & 7;
    int s = tid >> 3;
    int px = s & 7, py0 = s >> 3;

    u64 acc[4][4];
#pragma unroll
    for (int p = 0; p < 4; p++)
#pragma unroll
        for (int q = 0; q < 4; q++) acc[p][q] = 0ull;

    const float* xb = x + (size_t)b * NC * HWs;

    for (int cc = 0; cc < NC; cc += 16) {
        __syncthreads();
        // input tile + halo (same as R1)
        for (int idx = tid; idx < SMEM_IN_FLOATS; idx += 256) {
            int ch = idx / 324, rem = idx % 324;
            int iy = rem / 18, ix = rem % 18;
            int gy = ty0 + iy - 1, gx = tx0 + ix - 1;
            float v = 0.f;
            if ((unsigned)gy < 64u && (unsigned)gx < 64u)
                v = xb[(size_t)(cc + ch) * HWs + gy * 64 + gx];
            s_in[idx] = v;
        }
        // duplicated weights: 32 oc x 144 k
        for (int idx = tid; idx < 32 * 144; idx += 256) {
            int ocl = idx / 144, r = idx % 144;
            s_w2[idx] = g_w2[(size_t)(ocg * 32 + ocl) * KTOT + cc * 9 + r];
        }
        __syncthreads();

#pragma unroll
        for (int ic = 0; ic < 16; ic++) {
#pragma unroll
            for (int ky = 0; ky < 3; ky++) {
                u64 wv[3][4];
#pragma unroll
                for (int kx = 0; kx < 3; kx++)
#pragma unroll
                    for (int q = 0; q < 4; q++)
                        wv[kx][q] = *(const u64*)&s_w2[(o + 8 * q) * 144 + ic * 9 + ky * 3 + kx];
#pragma unroll
                for (int p = 0; p < 4; p++) {
                    int row = py0 + 4 * p + ky;
                    int base = ic * 324 + row * 18 + 2 * px;
                    u64 p01 = *(const u64*)&s_in[base];
                    u64 p23 = *(const u64*)&s_in[base + 2];
                    u64 p12 = (p01 >> 32) | (p23 << 32);
#pragma unroll
                    for (int q = 0; q < 4; q++) acc[p][q] = fma2(p01, wv[0][q], acc[p][q]);
#pragma unroll
                    for (int q = 0; q < 4; q++) acc[p][q] = fma2(p12, wv[1][q], acc[p][q]);
#pragma unroll
                    for (int q = 0; q < 4; q++) acc[p][q] = fma2(p23, wv[2][q], acc[p][q]);
                }
            }
        }
    }

    // epilogue: bias + relu, write g_h[b][oc][y][x] pairs
#pragma unroll
    for (int q = 0; q < 4; q++) {
        int oc = ocg * 32 + o + 8 * q;
        float bv = __ldg(bias + oc);
#pragma unroll
        for (int p = 0; p < 4; p++) {
            int y = ty0 + py0 + 4 * p;
            int xx = tx0 + 2 * px;
            float lo = __uint_as_float((uint32_t)acc[p][q]);
            float hi = __uint_as_float((uint32_t)(acc[p][q] >> 32));
            float2 r = make_float2(fmaxf(lo + bv, 0.f), fmaxf(hi + bv, 0.f));
            *(float2*)&g_h[((size_t)b * NC + oc) * HWs + y * 64 + xx] = r;
        }
    }
}

// ---------------- helpers ----------------
__device__ __forceinline__ unsigned int fdesc(float f) {
    unsigned int u = __float_as_uint(f);
    unsigned int asc = (u & 0x80000000u) ? ~u : (u | 0x80000000u);
    return ~asc;
}
__device__ __forceinline__ void base_anchor(int a, float& y1, float& x1, float& y2, float& x2) {
    int ri = a / 3, si = a % 3;
    double ratio = (ri == 0) ? 0.5 : (ri == 1 ? 1.0 : 2.0);
    double scale = (si == 0) ? 8.0 : (si == 1 ? 16.0 : 32.0);
    double h = 16.0 * scale * sqrt(ratio);
    double w = 16.0 * scale * sqrt(1.0 / ratio);
    y1 = (float)(8.0 - h * 0.5); x1 = (float)(8.0 - w * 0.5);
    y2 = (float)(8.0 + h * 0.5); x2 = (float)(8.0 + w * 0.5);
}

// ---------------- 1x1 heads + softmax + decode + sort-key pack (R1 version) ----------------
__global__ void __launch_bounds__(128) heads_kernel(const float* __restrict__ sw,
                                                    const float* __restrict__ sb,
                                                    const float* __restrict__ lw,
                                                    const float* __restrict__ lb,
                                                    float* __restrict__ out) {
    __shared__ float s_w[128 * 54];
    int b = blockIdx.y;
    int pos = blockIdx.x * 128 + threadIdx.x;

    float acc[54];
#pragma unroll
    for (int o = 0; o < 54; o++) acc[o] = 0.f;

    for (int c0 = 0; c0 < NC; c0 += 128) {
        __syncthreads();
        for (int idx = threadIdx.x; idx < 128 * 54; idx += 128) {
            int o = idx / 128, c = idx % 128;
            float v = (o < 18) ? sw[o * 512 + c0 + c] : lw[(o - 18) * 512 + c0 + c];
            s_w[c * 54 + o] = v;
        }
        __syncthreads();
        const float* hp = g_h + ((size_t)b * NC + c0) * HWs + pos;
        for (int c = 0; c < 128; c++) {
            float v = hp[(size_t)c * HWs];
            const float* wr = &s_w[c * 54];
#pragma unroll
            for (int o = 0; o < 54; o++) acc[o] = fmaf(v, wr[o], acc[o]);
        }
    }
#pragma unroll
    for (int o = 0; o < 18; o++) acc[o] += sb[o];
#pragma unroll
    for (int j = 0; j < 36; j++) acc[18 + j] += lb[j];

    float* os = out + (size_t)(b * HWs + pos) * 18;
#pragma unroll
    for (int o = 0; o < 18; o++) os[o] = acc[o];
    float* ol = out + OFF_LOCS + (size_t)(b * HWs + pos) * 36;
#pragma unroll
    for (int j = 0; j < 36; j++) ol[j] = acc[18 + j];

    int y = pos >> 6, xq = pos & 63;
    float fy = (float)(y * 16), fx = (float)(xq * 16);
#pragma unroll
    for (int a = 0; a < 9; a++) {
        float by1, bx1, by2, bx2;
        base_anchor(a, by1, bx1, by2, bx2);
        float ay1 = fy + by1, ax1 = fx + bx1, ay2 = fy + by2, ax2 = fx + bx2;
        float hA = ay2 - ay1, wA = ax2 - ax1;
        float cy = ay1 + 0.5f * hA, cx = ax1 + 0.5f * wA;
        float dy = acc[18 + 4 * a + 0], dx = acc[18 + 4 * a + 1];
        float dh = acc[18 + 4 * a + 2], dw = acc[18 + 4 * a + 3];
        float cty = dy * hA + cy, ctx = dx * wA + cx;
        float th = expf(dh) * hA, tw = expf(dw) * wA;
        float y1 = cty - 0.5f * th, x1 = ctx - 0.5f * tw;
        float y2 = cty + 0.5f * th, x2 = ctx + 0.5f * tw;
        y1 = fminf(fmaxf(y1, 0.f), 1024.f);
        y2 = fminf(fmaxf(y2, 0.f), 1024.f);
        x1 = fminf(fmaxf(x1, 0.f), 1024.f);
        x2 = fminf(fmaxf(x2, 0.f), 1024.f);
        bool valid = (y2 - y1 >= 16.f) && (x2 - x1 >= 16.f);

        float s0 = acc[2 * a], s1 = acc[2 * a + 1];
        float m = fmaxf(s0, s1);
        float e0 = expf(s0 - m), e1 = expf(s1 - m);
        float fg = e1 / (e0 + e1);
        float skey = valid ? fg : -INFINITY;

        int r = pos * 9 + a;
        size_t ro = ((size_t)b * NA + r) * 4;
        g_rois[ro + 0] = y1; g_rois[ro + 1] = x1;
        g_rois[ro + 2] = y2; g_rois[ro + 3] = x2;
        g_valid[b * NA + r] = valid ? 1 : 0;
        g_keys[(size_t)b * NSORT + r] = ((u64)fdesc(skey) << 32) | (unsigned)r;
    }
}

__global__ void pad_keys_kernel() {
    int gid = blockIdx.x * blockDim.x + threadIdx.x;
    int per = NSORT - NA;
    if (gid >= NB * per) return;
    int b = gid / per, i = NA + gid % per;
    g_keys[(size_t)b * NSORT + i] = ~0ull;
}

// ---------------- bitonic sort ----------------
__global__ void __launch_bounds__(1024) bitonic_local_sort() {
    __shared__ u64 s[4096];
    int base = blockIdx.x * 4096;
#pragma unroll
    for (int m = 0; m < 4; m++) s[threadIdx.x + 1024 * m] = g_keys[base + threadIdx.x + 1024 * m];
    for (int k = 2; k <= 4096; k <<= 1) {
        for (int j = k >> 1; j > 0; j >>= 1) {
            __syncthreads();
#pragma unroll
            for (int m = 0; m < 4; m++) {
                int i = threadIdx.x + 1024 * m;
                int p = i ^ j;
                if (p > i) {
                    int lidx = (base + i) & (NSORT - 1);
                    bool asc = ((lidx & k) == 0);
                    u64 av = s[i], bv = s[p];
                    if (asc ? (av > bv) : (av < bv)) { s[i] = bv; s[p] = av; }
                }
            }
        }
    }
    __syncthreads();
#pragma unroll
    for (int m = 0; m < 4; m++) g_keys[base + threadIdx.x + 1024 * m] = s[threadIdx.x + 1024 * m];
}

__global__ void __launch_bounds__(256) bitonic_global_step(int k, int j) {
    int gid = blockIdx.x * blockDim.x + threadIdx.x;
    int seg = gid >> 16, idx = gid & (NSORT - 1);
    int p = idx ^ j;
    if (p > idx) {
        bool asc = ((idx & k) == 0);
        u64* bptr = g_keys + ((size_t)seg << 16);
        u64 av = bptr[idx], bv = bptr[p];
        if (asc ? (av > bv) : (av < bv)) { bptr[idx] = bv; bptr[p] = av; }
    }
}

__global__ void __launch_bounds__(1024) bitonic_local_merge(int k) {
    __shared__ u64 s[4096];
    int base = blockIdx.x * 4096;
    bool asc = (((base & (NSORT - 1)) & k) == 0);
#pragma unroll
    for (int m = 0; m < 4; m++) s[threadIdx.x + 1024 * m] = g_keys[base + threadIdx.x + 1024 * m];
    for (int j = 2048; j > 0; j >>= 1) {
        __syncthreads();
#pragma unroll
        for (int m = 0; m < 4; m++) {
            int i = threadIdx.x + 1024 * m;
            int p = i ^ j;
            if (p > i) {
                u64 av = s[i], bv = s[p];
                if (asc ? (av > bv) : (av < bv)) { s[i] = bv; s[p] = av; }
            }
        }
    }
    __syncthreads();
#pragma unroll
    for (int m = 0; m < 4; m++) g_keys[base + threadIdx.x + 1024 * m] = s[threadIdx.x + 1024 * m];
}

__global__ void gather_kernel() {
    int gid = blockIdx.x * blockDim.x + threadIdx.x;
    if (gid >= NB * NIN) return;
    int b = gid / NIN, i = gid % NIN;
    u64 key = g_keys[(size_t)b * NSORT + i];
    unsigned r = (unsigned)(key & 0xffffffffu);
    size_t src = ((size_t)b * NA + r) * 4;
    size_t dst = ((size_t)b * NPAD + i) * 4;
    g_rois_s[dst + 0] = g_rois[src + 0];
    g_rois_s[dst + 1] = g_rois[src + 1];
    g_rois_s[dst + 2] = g_rois[src + 2];
    g_rois_s[dst + 3] = g_rois[src + 3];
    g_valid_s[b * NPAD + i] = g_valid[b * NA + r];
}

__global__ void __launch_bounds__(64) mask_kernel() {
    int rb = blockIdx.x, cb = blockIdx.y, b = blockIdx.z;
    if (cb < rb) return;
    __shared__ float4 sj[64];
    int u = threadIdx.x;
    const float4* rs = (const float4*)g_rois_s;
    sj[u] = rs[(size_t)b * NPAD + cb * 64 + u];
    __syncthreads();
    int i = rb * 64 + u;
    if (i >= NIN) return;
    float4 bi = rs[(size_t)b * NPAD + i];
    float ai = (bi.z - bi.x) * (bi.w - bi.y);
    u64 bits = 0;
#pragma unroll 8
    for (int q = 0; q < 64; q++) {
        int jj = cb * 64 + q;
        if (jj > i) {
            float4 bj = sj[q];
            float yy1 = fmaxf(bi.x, bj.x), xx1 = fmaxf(bi.y, bj.y);
            float yy2 = fminf(bi.z, bj.z), xx2 = fminf(bi.w, bj.w);
            float inter = fmaxf(yy2 - yy1, 0.f) * fmaxf(xx2 - xx1, 0.f);
            float aj = (bj.z - bj.x) * (bj.w - bj.y);
            float iou = inter / (ai + aj - inter + 1e-9f);
            if (iou > 0.7f) bits |= (1ull << q);
        }
    }
    g_mask[((size_t)b * NIN + i) * NWRD + cb] = bits;
}

__global__ void __launch_bounds__(32) nms_scan_kernel() {
    int b = blockIdx.x;
    int lane = threadIdx.x;
    const u64* mask = g_mask + (size_t)b * NIN * NWRD;
    const unsigned char* vs = g_valid_s + b * NPAD;
    unsigned char* keep = g_keep + b * NIN;
    int w0 = lane, w1 = lane + 32, w2 = lane + 64;
    bool has2 = (w2 < NWRD);
    u64 r0 = 0, r1 = 0, r2 = 0;
    u64 bufA[8][3], bufB[8][3];
    unsigned char vA[8], vB[8];
#pragma unroll
    for (int t = 0; t < 8; t++) {
        const u64* row = mask + (size_t)t * NWRD;
        bufA[t][0] = row[w0]; bufA[t][1] = row[w1];
        bufA[t][2] = has2 ? row[w2] : 0;
        vA[t] = vs[t];
    }
    for (int base = 0; base < NIN; base += 16) {
#pragma unroll
        for (int t = 0; t < 8; t++) {
            int ri = base + 8 + t;
            if (ri < NIN) {
                const u64* row = mask + (size_t)ri * NWRD;
                bufB[t][0] = row[w0]; bufB[t][1] = row[w1];
                bufB[t][2] = has2 ? row[w2] : 0;
                vB[t] = vs[ri];
            } else { bufB[t][0] = bufB[t][1] = bufB[t][2] = 0; vB[t] = 0; }
        }
#pragma unroll
        for (int t = 0; t < 8; t++) {
            int i = base + t;
            int iw = i >> 6;
            int sel = iw >> 5, owner = iw & 31;
            u64 myw = (sel == 0) ? r0 : ((sel == 1) ? r1 : r2);
            u64 wv = __shfl_sync(0xffffffffu, myw, owner);
            bool alive = vA[t] && !((wv >> (i & 63)) & 1ull);
            if (alive) { r0 |= bufA[t][0]; r1 |= bufA[t][1]; r2 |= bufA[t][2]; }
            if (lane == 0) keep[i] = alive ? 1 : 0;
        }
#pragma unroll
        for (int t = 0; t < 8; t++) {
            int ri = base + 16 + t;
            if (ri < NIN) {
                const u64* row = mask + (size_t)ri * NWRD;
                bufA[t][0] = row[w0]; bufA[t][1] = row[w1];
                bufA[t][2] = has2 ? row[w2] : 0;
                vA[t] = vs[ri];
            } else { bufA[t][0] = bufA[t][1] = bufA[t][2] = 0; vA[t] = 0; }
        }
#pragma unroll
        for (int t = 0; t < 8; t++) {
            int i = base + 8 + t;
            if (i >= NIN) break;
            int iw = i >> 6;
            int sel = iw >> 5, owner = iw & 31;
            u64 myw = (sel == 0) ? r0 : ((sel == 1) ? r1 : r2);
            u64 wv = __shfl_sync(0xffffffffu, myw, owner);
            bool alive = vB[t] && !((wv >> (i & 63)) & 1ull);
            if (alive) { r0 |= bufB[t][0]; r1 |= bufB[t][1]; r2 |= bufB[t][2]; }
            if (lane == 0) keep[i] = alive ? 1 : 0;
        }
    }
}

__global__ void misc_kernel(float* __restrict__ out) {
    int gid = blockIdx.x * blockDim.x + threadIdx.x;
    if (gid < NB * NOUTP * 4) out[OFF_ROIS + gid] = 0.f;
    if (gid < NB * NOUTP) out[OFF_INDS + gid] = (float)(gid / NOUTP);
}

__global__ void anchors_kernel(float* __restrict__ out) {
    int r = blockIdx.x * blockDim.x + threadIdx.x;
    if (r >= NA) return;
    int p = r / 9, a = r % 9;
    int y = p / 64, x = p % 64;
    float by1, bx1, by2, bx2;
    base_anchor(a, by1, bx1, by2, bx2);
    float fy = (float)(y * 16), fx = (float)(x * 16);
    float* o = out + OFF_ANCH + (size_t)r * 4;
    o[0] = fy + by1; o[1] = fx + bx1; o[2] = fy + by2; o[3] = fx + bx2;
}

__global__ void __launch_bounds__(256) finalize_kernel(float* __restrict__ out) {
    int b = blockIdx.x;
    int tid = threadIdx.x;
    __shared__ int ssum[256];
    const unsigned char* keep = g_keep + b * NIN;
    unsigned char kl[24];
    int start = tid * 24;
    int cnt = 0;
#pragma unroll
    for (int t = 0; t < 24; t++) {
        int i = start + t;
        kl[t] = (i < NIN) ? keep[i] : 0;
        cnt += kl[t];
    }
    ssum[tid] = cnt;
    __syncthreads();
    for (int off = 1; off < 256; off <<= 1) {
        int v = (tid >= off) ? ssum[tid - off] : 0;
        __syncthreads();
        ssum[tid] += v;
        __syncthreads();
    }
    int r = ssum[tid] - cnt;
    const float4* rs = (const float4*)g_rois_s;
#pragma unroll
    for (int t = 0; t < 24; t++) {
        if (kl[t]) {
            if (r < NOUTP) {
                int i = start + t;
                float4 bx = rs[(size_t)b * NPAD + i];
                float* o = out + OFF_ROIS + (size_t)(b * NOUTP + r) * 4;
                o[0] = bx.x; o[1] = bx.y; o[2] = bx.z; o[3] = bx.w;
            }
            r++;
        }
    }
}

// ---------------- launch ----------------
extern "C" void kernel_launch(void* const* d_in, const int* in_sizes, int n_in,
                              void* d_out, int out_size) {
    const float* x       = (const float*)d_in[0];
    const float* conv_w  = (const float*)d_in[1];
    const float* conv_b  = (const float*)d_in[2];
    const float* score_w = (const float*)d_in[3];
    const float* score_b = (const float*)d_in[4];
    const float* loc_w   = (const float*)d_in[5];
    const float* loc_b   = (const float*)d_in[6];
    float* out = (float*)d_out;

    cudaFuncSetAttribute(conv_f32x2_kernel, cudaFuncAttributeMaxDynamicSharedMemorySize,
                         SMEM_CONV_TOTAL);

    prep_w2_kernel<<<(NC * KTOT + 255) / 256, 256>>>(conv_w);
    conv_f32x2_kernel<<<dim3(16, 16, NB), 256, SMEM_CONV_TOTAL>>>(x, conv_b);
    heads_kernel<<<dim3(32, NB), 128>>>(score_w, score_b, loc_w, loc_b, out);
    pad_keys_kernel<<<(NB * (NSORT - NA) + 255) / 256, 256>>>();

    bitonic_local_sort<<<NB * NSORT / 4096, 1024>>>();
    for (int k = 8192; k <= NSORT; k <<= 1) {
        for (int j = k >> 1; j >= 4096; j >>= 1)
            bitonic_global_step<<<NB * NSORT / 256, 256>>>(k, j);
        bitonic_local_merge<<<NB * NSORT / 4096, 1024>>>(k);
    }

    gather_kernel<<<(NB * NIN + 255) / 256, 256>>>();
    mask_kernel<<<dim3(NWRD, NWRD, NB), 64>>>();
    nms_scan_kernel<<<NB, 32>>>();
    misc_kernel<<<(NB * NOUTP * 4 + 255) / 256, 256>>>(out);
    anchors_kernel<<<(NA + 255) / 256, 256>>>(out);
    finalize_kernel<<<NB, 256>>>(out);
}

// round 6
// speedup vs baseline: 4.3141x; 4.3141x over previous
#include <cuda_runtime.h>
#include <math.h>
#include <stdint.h>

#define NB   4
#define NC   512
#define HWs  4096
#define NA   36864
#define NSORT 65536
#define NIN  6000
#define NWRD 94
#define NPAD 6016
#define NOUTP 300
#define KTOT 4608
#define NCHUNK 288     // K chunks of 16

#define OFF_LOCS 294912
#define OFF_ROIS 884736
#define OFF_INDS 889536
#define OFF_ANCH 890736

typedef unsigned long long u64;

// ---------------- scratch ----------------
__device__ float g_h[(size_t)NB * HWs * NC];   // layout [b][sp][oc]
__device__ float g_w_hi[(size_t)NC * KTOT];
__device__ float g_w_lo[(size_t)NC * KTOT];
__device__ float g_rois[(size_t)NB * NA * 4];
__device__ unsigned char g_valid[NB * NA];
__device__ u64 g_keys[NB * NSORT];
__device__ float g_rois_s[NB * NPAD * 4];
__device__ unsigned char g_valid_s[NB * NPAD];
__device__ u64 g_mask[(size_t)NB * NIN * NWRD];
__device__ unsigned char g_keep[NB * NIN];

static __device__ __forceinline__ uint32_t cvt_tf32(float v) {
    uint32_t r;
    asm("cvt.rna.tf32.f32 %0, %1;" : "=r"(r) : "f"(v));
    return r;
}

// d = a*b + c  (explicit C so chains can start from zero)
#define MMA_TF32(d, a, b, c) \
    asm volatile("mma.sync.aligned.m16n8k8.row.col.f32.tf32.tf32.f32 " \
        "{%0,%1,%2,%3}, {%4,%5,%6,%7}, {%8,%9}, {%10,%11,%12,%13};" \
        : "=f"((d)[0]), "=f"((d)[1]), "=f"((d)[2]), "=f"((d)[3]) \
        : "r"((a)[0]), "r"((a)[1]), "r"((a)[2]), "r"((a)[3]), \
          "r"((b)[0]), "r"((b)[1]), \
          "f"((c)[0]), "f"((c)[1]), "f"((c)[2]), "f"((c)[3]))

// ---------------- weight hi/lo split ----------------
__global__ void prep_w_kernel(const float* __restrict__ w) {
    int gid = blockIdx.x * blockDim.x + threadIdx.x;
    if (gid >= NC * KTOT) return;
    float v = w[gid];
    uint32_t hi = cvt_tf32(v);
    float lo = v - __uint_as_float(hi);
    g_w_hi[gid] = __uint_as_float(hi);
    g_w_lo[gid] = __uint_as_float(cvt_tf32(lo));
}

// ---------------- tf32 mma.sync conv (4-product + register drains) ----------------
// grid (32 sp-tiles, 4 oc-tiles, 4 batch), 256 threads (8 warps, 2x4 warp grid).
__global__ void __launch_bounds__(256) conv_mma_kernel(const float* __restrict__ x,
                                                       const float* __restrict__ bias) {
    __shared__ float sA_hi[128 * 17];
    __shared__ float sA_lo[128 * 17];
    __shared__ float sW_hi[128 * 17];
    __shared__ float sW_lo[128 * 17];

    int tid = threadIdx.x;
    int warp = tid >> 5, lane = tid & 31;
    int gid = lane >> 2, tig = lane & 3;
    int b = blockIdx.z, spt = blockIdx.x, ocg = blockIdx.y;
    int sp0 = spt * 128, oc0 = ocg * 128;
    int wm = warp & 1, wn = warp >> 1;

    float acc[4][4][4];
#pragma unroll
    for (int mf = 0; mf < 4; mf++)
#pragma unroll
        for (int nf = 0; nf < 4; nf++)
#pragma unroll
            for (int q = 0; q < 4; q++) acc[mf][nf][q] = 0.f;

    const float* xb = x + (size_t)b * NC * HWs;

    // loader roles
    int spl = tid & 127;             // A: spatial lane
    int j0 = tid >> 7;               // A: k-parity (0/1)
    int y = (sp0 + spl) >> 6, xq = (sp0 + spl) & 63;
    int ocl = tid >> 1;              // W: oc lane
    int kl0 = (tid & 1) * 8;         // W: k-half

    float vA[8];
    float4 wh0, wh1, wl0, wl1;

    // prologue: prefetch chunk 0
#pragma unroll
    for (int i = 0; i < 8; i++) {
        int kg = j0 + 2 * i;
        int ic = kg / 9, t = kg - ic * 9;
        int yy = y + t / 3 - 1, xx = xq + t % 3 - 1;
        bool ok = ((unsigned)yy < 64u) & ((unsigned)xx < 64u);
        vA[i] = ok ? __ldg(xb + (size_t)ic * HWs + yy * 64 + xx) : 0.f;
    }
    {
        const float4* ph = (const float4*)(g_w_hi + (size_t)(oc0 + ocl) * KTOT + kl0);
        const float4* pl = (const float4*)(g_w_lo + (size_t)(oc0 + ocl) * KTOT + kl0);
        wh0 = ph[0]; wh1 = ph[1]; wl0 = pl[0]; wl1 = pl[1];
    }

    for (int c = 0; c < NCHUNK; c++) {
        // store prefetched chunk into smem (convert A on the fly)
#pragma unroll
        for (int i = 0; i < 8; i++) {
            int j = j0 + 2 * i;
            uint32_t hi = cvt_tf32(vA[i]);
            float lo = vA[i] - __uint_as_float(hi);
            sA_hi[spl * 17 + j] = __uint_as_float(hi);
            sA_lo[spl * 17 + j] = __uint_as_float(cvt_tf32(lo));
        }
        {
            float* dh = &sW_hi[ocl * 17 + kl0];
            float* dl = &sW_lo[ocl * 17 + kl0];
            dh[0] = wh0.x; dh[1] = wh0.y; dh[2] = wh0.z; dh[3] = wh0.w;
            dh[4] = wh1.x; dh[5] = wh1.y; dh[6] = wh1.z; dh[7] = wh1.w;
            dl[0] = wl0.x; dl[1] = wl0.y; dl[2] = wl0.z; dl[3] = wl0.w;
            dl[4] = wl1.x; dl[5] = wl1.y; dl[6] = wl1.z; dl[7] = wl1.w;
        }
        __syncthreads();

        // prefetch next chunk (LDG latency hidden under MMAs below)
        if (c + 1 < NCHUNK) {
            int cn = c + 1;
#pragma unroll
            for (int i = 0; i < 8; i++) {
                int kg = cn * 16 + j0 + 2 * i;
                int ic = kg / 9, t = kg - ic * 9;
                int yy = y + t / 3 - 1, xx = xq + t % 3 - 1;
                bool ok = ((unsigned)yy < 64u) & ((unsigned)xx < 64u);
                vA[i] = ok ? __ldg(xb + (size_t)ic * HWs + yy * 64 + xx) : 0.f;
            }
            const float4* ph = (const float4*)(g_w_hi + (size_t)(oc0 + ocl) * KTOT + cn * 16 + kl0);
            const float4* pl = (const float4*)(g_w_lo + (size_t)(oc0 + ocl) * KTOT + cn * 16 + kl0);
            wh0 = ph[0]; wh1 = ph[1]; wl0 = pl[0]; wl1 = pl[1];
        }

        // MMA on current chunk: per k-step, fresh tensor chain of 4 products,
        // then drain into fp32 register accumulators (rn adds).
#pragma unroll
        for (int ks = 0; ks < 2; ks++) {
            int kb = ks * 8;
            uint32_t Ah[4][4], Al[4][4], Bh[4][2], Bl[4][2];
#pragma unroll
            for (int mf = 0; mf < 4; mf++) {
                int ar = wm * 64 + mf * 16 + gid;
                Ah[mf][0] = __float_as_uint(sA_hi[ar * 17 + kb + tig]);
                Ah[mf][1] = __float_as_uint(sA_hi[(ar + 8) * 17 + kb + tig]);
                Ah[mf][2] = __float_as_uint(sA_hi[ar * 17 + kb + tig + 4]);
                Ah[mf][3] = __float_as_uint(sA_hi[(ar + 8) * 17 + kb + tig + 4]);
                Al[mf][0] = __float_as_uint(sA_lo[ar * 17 + kb + tig]);
                Al[mf][1] = __float_as_uint(sA_lo[(ar + 8) * 17 + kb + tig]);
                Al[mf][2] = __float_as_uint(sA_lo[ar * 17 + kb + tig + 4]);
                Al[mf][3] = __float_as_uint(sA_lo[(ar + 8) * 17 + kb + tig + 4]);
            }
#pragma unroll
            for (int nf = 0; nf < 4; nf++) {
                int bc = wn * 32 + nf * 8 + gid;
                Bh[nf][0] = __float_as_uint(sW_hi[bc * 17 + kb + tig]);
                Bh[nf][1] = __float_as_uint(sW_hi[bc * 17 + kb + tig + 4]);
                Bl[nf][0] = __float_as_uint(sW_lo[bc * 17 + kb + tig]);
                Bl[nf][1] = __float_as_uint(sW_lo[bc * 17 + kb + tig + 4]);
            }
            const float zero4[4] = {0.f, 0.f, 0.f, 0.f};
#pragma unroll
            for (int mf = 0; mf < 4; mf++)
#pragma unroll
                for (int nf = 0; nf < 4; nf++) {
                    float d[4];
                    MMA_TF32(d, Ah[mf], Bh[nf], zero4);
                    MMA_TF32(d, Ah[mf], Bl[nf], d);
                    MMA_TF32(d, Al[mf], Bh[nf], d);
                    MMA_TF32(d, Al[mf], Bl[nf], d);
#pragma unroll
                    for (int q = 0; q < 4; q++) acc[mf][nf][q] += d[q];
                }
        }
        __syncthreads();
    }

    // epilogue: bias + relu, write g_h[b][sp][oc]
#pragma unroll
    for (int nf = 0; nf < 4; nf++) {
        int col = oc0 + wn * 32 + nf * 8 + 2 * tig;
        float bv0 = __ldg(bias + col), bv1 = __ldg(bias + col + 1);
#pragma unroll
        for (int mf = 0; mf < 4; mf++) {
            int row = sp0 + wm * 64 + mf * 16 + gid;
            size_t b0 = ((size_t)b * HWs + row) * NC + col;
            size_t b1 = ((size_t)b * HWs + row + 8) * NC + col;
            g_h[b0]     = fmaxf(acc[mf][nf][0] + bv0, 0.f);
            g_h[b0 + 1] = fmaxf(acc[mf][nf][1] + bv1, 0.f);
            g_h[b1]     = fmaxf(acc[mf][nf][2] + bv0, 0.f);
            g_h[b1 + 1] = fmaxf(acc[mf][nf][3] + bv1, 0.f);
        }
    }
}

// ---------------- helpers ----------------
__device__ __forceinline__ unsigned int fdesc(float f) {
    unsigned int u = __float_as_uint(f);
    unsigned int asc = (u & 0x80000000u) ? ~u : (u | 0x80000000u);
    return ~asc;
}
__device__ __forceinline__ void base_anchor(int a, float& y1, float& x1, float& y2, float& x2) {
    int ri = a / 3, si = a % 3;
    double ratio = (ri == 0) ? 0.5 : (ri == 1 ? 1.0 : 2.0);
    double scale = (si == 0) ? 8.0 : (si == 1 ? 16.0 : 32.0);
    double h = 16.0 * scale * sqrt(ratio);
    double w = 16.0 * scale * sqrt(1.0 / ratio);
    y1 = (float)(8.0 - h * 0.5); x1 = (float)(8.0 - w * 0.5);
    y2 = (float)(8.0 + h * 0.5); x2 = (float)(8.0 + w * 0.5);
}

// ---------------- 1x1 heads + softmax + decode + sort-key pack ----------------
__global__ void __launch_bounds__(128) heads_kernel(const float* __restrict__ sw,
                                                    const float* __restrict__ sb,
                                                    const float* __restrict__ lw,
                                                    const float* __restrict__ lb,
                                                    float* __restrict__ out) {
    __shared__ float s_w[128 * 54];
    int b = blockIdx.y;
    int pos = blockIdx.x * 128 + threadIdx.x;

    float acc[54];
#pragma unroll
    for (int o = 0; o < 54; o++) acc[o] = 0.f;

    for (int c0 = 0; c0 < NC; c0 += 128) {
        __syncthreads();
        for (int idx = threadIdx.x; idx < 128 * 54; idx += 128) {
            int o = idx / 128, c = idx % 128;
            float v = (o < 18) ? sw[o * 512 + c0 + c] : lw[(o - 18) * 512 + c0 + c];
            s_w[c * 54 + o] = v;
        }
        __syncthreads();
        const float4* hp4 = (const float4*)(g_h + ((size_t)b * HWs + pos) * NC + c0);
        for (int c4 = 0; c4 < 32; c4++) {
            float4 v = hp4[c4];
            const float* w0 = &s_w[(c4 * 4 + 0) * 54];
            const float* w1 = &s_w[(c4 * 4 + 1) * 54];
            const float* w2 = &s_w[(c4 * 4 + 2) * 54];
            const float* w3 = &s_w[(c4 * 4 + 3) * 54];
#pragma unroll
            for (int o = 0; o < 54; o++) {
                acc[o] = fmaf(v.x, w0[o], acc[o]);
                acc[o] = fmaf(v.y, w1[o], acc[o]);
                acc[o] = fmaf(v.z, w2[o], acc[o]);
                acc[o] = fmaf(v.w, w3[o], acc[o]);
            }
        }
    }
#pragma unroll
    for (int o = 0; o < 18; o++) acc[o] += sb[o];
#pragma unroll
    for (int j = 0; j < 36; j++) acc[18 + j] += lb[j];

    float* os = out + (size_t)(b * HWs + pos) * 18;
#pragma unroll
    for (int o = 0; o < 18; o++) os[o] = acc[o];
    float* ol = out + OFF_LOCS + (size_t)(b * HWs + pos) * 36;
#pragma unroll
    for (int j = 0; j < 36; j++) ol[j] = acc[18 + j];

    int y = pos >> 6, xq = pos & 63;
    float fy = (float)(y * 16), fx = (float)(xq * 16);
#pragma unroll
    for (int a = 0; a < 9; a++) {
        float by1, bx1, by2, bx2;
        base_anchor(a, by1, bx1, by2, bx2);
        float ay1 = fy + by1, ax1 = fx + bx1, ay2 = fy + by2, ax2 = fx + bx2;
        float hA = ay2 - ay1, wA = ax2 - ax1;
        float cy = ay1 + 0.5f * hA, cx = ax1 + 0.5f * wA;
        float dy = acc[18 + 4 * a + 0], dx = acc[18 + 4 * a + 1];
        float dh = acc[18 + 4 * a + 2], dw = acc[18 + 4 * a + 3];
        float cty = dy * hA + cy, ctx = dx * wA + cx;
        float th = expf(dh) * hA, tw = expf(dw) * wA;
        float y1 = cty - 0.5f * th, x1 = ctx - 0.5f * tw;
        float y2 = cty + 0.5f * th, x2 = ctx + 0.5f * tw;
        y1 = fminf(fmaxf(y1, 0.f), 1024.f);
        y2 = fminf(fmaxf(y2, 0.f), 1024.f);
        x1 = fminf(fmaxf(x1, 0.f), 1024.f);
        x2 = fminf(fmaxf(x2, 0.f), 1024.f);
        bool valid = (y2 - y1 >= 16.f) && (x2 - x1 >= 16.f);

        float s0 = acc[2 * a], s1 = acc[2 * a + 1];
        float m = fmaxf(s0, s1);
        float e0 = expf(s0 - m), e1 = expf(s1 - m);
        float fg = e1 / (e0 + e1);
        float skey = valid ? fg : -INFINITY;

        int r = pos * 9 + a;
        size_t ro = ((size_t)b * NA + r) * 4;
        g_rois[ro + 0] = y1; g_rois[ro + 1] = x1;
        g_rois[ro + 2] = y2; g_rois[ro + 3] = x2;
        g_valid[b * NA + r] = valid ? 1 : 0;
        g_keys[(size_t)b * NSORT + r] = ((u64)fdesc(skey) << 32) | (unsigned)r;
    }
}

__global__ void pad_keys_kernel() {
    int gid = blockIdx.x * blockDim.x + threadIdx.x;
    int per = NSORT - NA;
    if (gid >= NB * per) return;
    int b = gid / per, i = NA + gid % per;
    g_keys[(size_t)b * NSORT + i] = ~0ull;
}

// ---------------- bitonic sort ----------------
__global__ void __launch_bounds__(1024) bitonic_local_sort() {
    __shared__ u64 s[4096];
    int base = blockIdx.x * 4096;
#pragma unroll
    for (int m = 0; m < 4; m++) s[threadIdx.x + 1024 * m] = g_keys[base + threadIdx.x + 1024 * m];
    for (int k = 2; k <= 4096; k <<= 1) {
        for (int j = k >> 1; j > 0; j >>= 1) {
            __syncthreads();
#pragma unroll
            for (int m = 0; m < 4; m++) {
                int i = threadIdx.x + 1024 * m;
                int p = i ^ j;
                if (p > i) {
                    int lidx = (base + i) & (NSORT - 1);
                    bool asc = ((lidx & k) == 0);
                    u64 av = s[i], bv = s[p];
                    if (asc ? (av > bv) : (av < bv)) { s[i] = bv; s[p] = av; }
                }
            }
        }
    }
    __syncthreads();
#pragma unroll
    for (int m = 0; m < 4; m++) g_keys[base + threadIdx.x + 1024 * m] = s[threadIdx.x + 1024 * m];
}

__global__ void __launch_bounds__(256) bitonic_global_step(int k, int j) {
    int gid = blockIdx.x * blockDim.x + threadIdx.x;
    int seg = gid >> 16, idx = gid & (NSORT - 1);
    int p = idx ^ j;
    if (p > idx) {
        bool asc = ((idx & k) == 0);
        u64* bptr = g_keys + ((size_t)seg << 16);
        u64 av = bptr[idx], bv = bptr[p];
        if (asc ? (av > bv) : (av < bv)) { bptr[idx] = bv; bptr[p] = av; }
    }
}

__global__ void __launch_bounds__(1024) bitonic_local_merge(int k) {
    __shared__ u64 s[4096];
    int base = blockIdx.x * 4096;
    bool asc = (((base & (NSORT - 1)) & k) == 0);
#pragma unroll
    for (int m = 0; m < 4; m++) s[threadIdx.x + 1024 * m] = g_keys[base + threadIdx.x + 1024 * m];
    for (int j = 2048; j > 0; j >>= 1) {
        __syncthreads();
#pragma unroll
        for (int m = 0; m < 4; m++) {
            int i = threadIdx.x + 1024 * m;
            int p = i ^ j;
            if (p > i) {
                u64 av = s[i], bv = s[p];
                if (asc ? (av > bv) : (av < bv)) { s[i] = bv; s[p] = av; }
            }
        }
    }
    __syncthreads();
#pragma unroll
    for (int m = 0; m < 4; m++) g_keys[base + threadIdx.x + 1024 * m] = s[threadIdx.x + 1024 * m];
}

__global__ void gather_kernel() {
    int gid = blockIdx.x * blockDim.x + threadIdx.x;
    if (gid >= NB * NIN) return;
    int b = gid / NIN, i = gid % NIN;
    u64 key = g_keys[(size_t)b * NSORT + i];
    unsigned r = (unsigned)(key & 0xffffffffu);
    size_t src = ((size_t)b * NA + r) * 4;
    size_t dst = ((size_t)b * NPAD + i) * 4;
    g_rois_s[dst + 0] = g_rois[src + 0];
    g_rois_s[dst + 1] = g_rois[src + 1];
    g_rois_s[dst + 2] = g_rois[src + 2];
    g_rois_s[dst + 3] = g_rois[src + 3];
    g_valid_s[b * NPAD + i] = g_valid[b * NA + r];
}

__global__ void __launch_bounds__(64) mask_kernel() {
    int rb = blockIdx.x, cb = blockIdx.y, b = blockIdx.z;
    if (cb < rb) return;
    __shared__ float4 sj[64];
    int u = threadIdx.x;
    const float4* rs = (const float4*)g_rois_s;
    sj[u] = rs[(size_t)b * NPAD + cb * 64 + u];
    __syncthreads();
    int i = rb * 64 + u;
    if (i >= NIN) return;
    float4 bi = rs[(size_t)b * NPAD + i];
    float ai = (bi.z - bi.x) * (bi.w - bi.y);
    u64 bits = 0;
#pragma unroll 8
    for (int q = 0; q < 64; q++) {
        int jj = cb * 64 + q;
        if (jj > i) {
            float4 bj = sj[q];
            float yy1 = fmaxf(bi.x, bj.x), xx1 = fmaxf(bi.y, bj.y);
            float yy2 = fminf(bi.z, bj.z), xx2 = fminf(bi.w, bj.w);
            float inter = fmaxf(yy2 - yy1, 0.f) * fmaxf(xx2 - xx1, 0.f);
            float aj = (bj.z - bj.x) * (bj.w - bj.y);
            float iou = inter / (ai + aj - inter + 1e-9f);
            if (iou > 0.7f) bits |= (1ull << q);
        }
    }
    g_mask[((size_t)b * NIN + i) * NWRD + cb] = bits;
}

__global__ void __launch_bounds__(32) nms_scan_kernel() {
    int b = blockIdx.x;
    int lane = threadIdx.x;
    const u64* mask = g_mask + (size_t)b * NIN * NWRD;
    const unsigned char* vs = g_valid_s + b * NPAD;
    unsigned char* keep = g_keep + b * NIN;
    int w0 = lane, w1 = lane + 32, w2 = lane + 64;
    bool has2 = (w2 < NWRD);
    u64 r0 = 0, r1 = 0, r2 = 0;
    u64 bufA[8][3], bufB[8][3];
    unsigned char vA[8], vB[8];
#pragma unroll
    for (int t = 0; t < 8; t++) {
        const u64* row = mask + (size_t)t * NWRD;
        bufA[t][0] = row[w0]; bufA[t][1] = row[w1];
        bufA[t][2] = has2 ? row[w2] : 0;
        vA[t] = vs[t];
    }
    for (int base = 0; base < NIN; base += 16) {
#pragma unroll
        for (int t = 0; t < 8; t++) {
            int ri = base + 8 + t;
            if (ri < NIN) {
                const u64* row = mask + (size_t)ri * NWRD;
                bufB[t][0] = row[w0]; bufB[t][1] = row[w1];
                bufB[t][2] = has2 ? row[w2] : 0;
                vB[t] = vs[ri];
            } else { bufB[t][0] = bufB[t][1] = bufB[t][2] = 0; vB[t] = 0; }
        }
#pragma unroll
        for (int t = 0; t < 8; t++) {
            int i = base + t;
            int iw = i >> 6;
            int sel = iw >> 5, owner = iw & 31;
            u64 myw = (sel == 0) ? r0 : ((sel == 1) ? r1 : r2);
            u64 wv = __shfl_sync(0xffffffffu, myw, owner);
            bool alive = vA[t] && !((wv >> (i & 63)) & 1ull);
            if (alive) { r0 |= bufA[t][0]; r1 |= bufA[t][1]; r2 |= bufA[t][2]; }
            if (lane == 0) keep[i] = alive ? 1 : 0;
        }
#pragma unroll
        for (int t = 0; t < 8; t++) {
            int ri = base + 16 + t;
            if (ri < NIN) {
                const u64* row = mask + (size_t)ri * NWRD;
                bufA[t][0] = row[w0]; bufA[t][1] = row[w1];
                bufA[t][2] = has2 ? row[w2] : 0;
                vA[t] = vs[ri];
            } else { bufA[t][0] = bufA[t][1] = bufA[t][2] = 0; vA[t] = 0; }
        }
#pragma unroll
        for (int t = 0; t < 8; t++) {
            int i = base + 8 + t;
            if (i >= NIN) break;
            int iw = i >> 6;
            int sel = iw >> 5, owner = iw & 31;
            u64 myw = (sel == 0) ? r0 : ((sel == 1) ? r1 : r2);
            u64 wv = __shfl_sync(0xffffffffu, myw, owner);
            bool alive = vB[t] && !((wv >> (i & 63)) & 1ull);
            if (alive) { r0 |= bufB[t][0]; r1 |= bufB[t][1]; r2 |= bufB[t][2]; }
            if (lane == 0) keep[i] = alive ? 1 : 0;
        }
    }
}

__global__ void misc_kernel(float* __restrict__ out) {
    int gid = blockIdx.x * blockDim.x + threadIdx.x;
    if (gid < NB * NOUTP * 4) out[OFF_ROIS + gid] = 0.f;
    if (gid < NB * NOUTP) out[OFF_INDS + gid] = (float)(gid / NOUTP);
}

__global__ void anchors_kernel(float* __restrict__ out) {
    int r = blockIdx.x * blockDim.x + threadIdx.x;
    if (r >= NA) return;
    int p = r / 9, a = r % 9;
    int y = p / 64, x = p % 64;
    float by1, bx1, by2, bx2;
    base_anchor(a, by1, bx1, by2, bx2);
    float fy = (float)(y * 16), fx = (float)(x * 16);
    float* o = out + OFF_ANCH + (size_t)r * 4;
    o[0] = fy + by1; o[1] = fx + bx1; o[2] = fy + by2; o[3] = fx + bx2;
}

__global__ void __launch_bounds__(256) finalize_kernel(float* __restrict__ out) {
    int b = blockIdx.x;
    int tid = threadIdx.x;
    __shared__ int ssum[256];
    const unsigned char* keep = g_keep + b * NIN;
    unsigned char kl[24];
    int start = tid * 24;
    int cnt = 0;
#pragma unroll
    for (int t = 0; t < 24; t++) {
        int i = start + t;
        kl[t] = (i < NIN) ? keep[i] : 0;
        cnt += kl[t];
    }
    ssum[tid] = cnt;
    __syncthreads();
    for (int off = 1; off < 256; off <<= 1) {
        int v = (tid >= off) ? ssum[tid - off] : 0;
        __syncthreads();
        ssum[tid] += v;
        __syncthreads();
    }
    int r = ssum[tid] - cnt;
    const float4* rs = (const float4*)g_rois_s;
#pragma unroll
    for (int t = 0; t < 24; t++) {
        if (kl[t]) {
            if (r < NOUTP) {
                int i = start + t;
                float4 bx = rs[(size_t)b * NPAD + i];
                float* o = out + OFF_ROIS + (size_t)(b * NOUTP + r) * 4;
                o[0] = bx.x; o[1] = bx.y; o[2] = bx.z; o[3] = bx.w;
            }
            r++;
        }
    }
}

// ---------------- launch ----------------
extern "C" void kernel_launch(void* const* d_in, const int* in_sizes, int n_in,
                              void* d_out, int out_size) {
    const float* x       = (const float*)d_in[0];
    const float* conv_w  = (const float*)d_in[1];
    const float* conv_b  = (const float*)d_in[2];
    const float* score_w = (const float*)d_in[3];
    const float* score_b = (const float*)d_in[4];
    const float* loc_w   = (const float*)d_in[5];
    const float* loc_b   = (const float*)d_in[6];
    float* out = (float*)d_out;

    prep_w_kernel<<<(NC * KTOT + 255) / 256, 256>>>(conv_w);
    conv_mma_kernel<<<dim3(32, 4, NB), 256>>>(x, conv_b);
    heads_kernel<<<dim3(32, NB), 128>>>(score_w, score_b, loc_w, loc_b, out);
    pad_keys_kernel<<<(NB * (NSORT - NA) + 255) / 256, 256>>>();

    bitonic_local_sort<<<NB * NSORT / 4096, 1024>>>();
    for (int k = 8192; k <= NSORT; k <<= 1) {
        for (int j = k >> 1; j >= 4096; j >>= 1)
            bitonic_global_step<<<NB * NSORT / 256, 256>>>(k, j);
        bitonic_local_merge<<<NB * NSORT / 4096, 1024>>>(k);
    }

    gather_kernel<<<(NB * NIN + 255) / 256, 256>>>();
    mask_kernel<<<dim3(NWRD, NWRD, NB), 64>>>();
    nms_scan_kernel<<<NB, 32>>>();
    misc_kernel<<<(NB * NOUTP * 4 + 255) / 256, 256>>>(out);
    anchors_kernel<<<(NA + 255) / 256, 256>>>(out);
    finalize_kernel<<<NB, 256>>>(out);
}